// round 17
// baseline (speedup 1.0000x reference)
#include <cuda_runtime.h>
#include <cuda_fp16.h>
#include <cstdint>

// B=2,H=16,S=2048,D=64 causal attention, fp32 in/out.
#define BHN   32
#define SEQ   2048
#define DH    64
#define BM    128                       // q rows per CTA (4 warps x 2 halves x 16)
#define BN    64
#define NTHR  128
#define NELEM (BHN * SEQ * DH)          // 4,194,304

#define QSCALE 0.18033688f              // 0.125 * log2(e)
#define ONESH2 0x3C003C00u              // fp16x2 {1.0, 1.0}

// ---- pre-converted fp16 operands ----
__device__ __align__(16) uint8_t gKhi[NELEM * 2];
__device__ __align__(16) uint8_t gVhi[NELEM * 2];

// ---- smem: 4 stages x 16KB (KHI|VHI, 8KB each, XOR-swizzled) ----
#define STAGE   16384
#define P_KHI   0
#define P_VHI   8192
#define SMEM_BYTES (4 * STAGE)          // 65536 -> 2 CTAs/SM (128KB)

__device__ __forceinline__ uint32_t smem_u32(const void* p) {
    uint32_t a;
    asm("{ .reg .u64 t; cvta.to.shared.u64 t, %1; cvt.u32.u64 %0, t; }" : "=r"(a) : "l"(p));
    return a;
}
__device__ __forceinline__ uint32_t swz(uint32_t b) { return b ^ ((b >> 3) & 0x70u); }
__device__ __forceinline__ float ex2(float x) {
    float r; asm("ex2.approx.f32 %0, %1;" : "=f"(r) : "f"(x)); return r;
}
__device__ __forceinline__ uint32_t ex2h2(uint32_t x) {
    uint32_t r; asm("ex2.approx.f16x2 %0, %1;" : "=r"(r) : "r"(x)); return r;
}
__device__ __forceinline__ uint32_t maxh2(uint32_t a, uint32_t b) {
    uint32_t r; asm("max.f16x2 %0, %1, %2;" : "=r"(r) : "r"(a), "r"(b)); return r;
}
__device__ __forceinline__ float h2lo_f32(uint32_t h) {
    float r; asm("{ .reg .b16 x, y; mov.b32 {x, y}, %1; cvt.f32.f16 %0, x; }"
                 : "=f"(r) : "r"(h));
    return r;
}
__device__ __forceinline__ float h2hi_f32(uint32_t h) {
    float r; asm("{ .reg .b16 x, y; mov.b32 {x, y}, %1; cvt.f32.f16 %0, y; }"
                 : "=f"(r) : "r"(h));
    return r;
}
__device__ __forceinline__ void cpa16(uint32_t dst, const void* src) {
    asm volatile("cp.async.cg.shared.global [%0], [%1], 16;" :: "r"(dst), "l"(src));
}
#define CP_COMMIT() asm volatile("cp.async.commit_group;" ::: "memory")
#define CP_WAIT(n)  asm volatile("cp.async.wait_group %0;" :: "n"(n) : "memory")

__device__ __forceinline__ void ldsm4(uint32_t r[4], uint32_t addr) {
    asm volatile("ldmatrix.sync.aligned.m8n8.x4.shared.b16 {%0,%1,%2,%3}, [%4];"
        : "=r"(r[0]), "=r"(r[1]), "=r"(r[2]), "=r"(r[3]) : "r"(addr));
}
__device__ __forceinline__ void ldsm4t(uint32_t r[4], uint32_t addr) {
    asm volatile("ldmatrix.sync.aligned.m8n8.x4.trans.shared.b16 {%0,%1,%2,%3}, [%4];"
        : "=r"(r[0]), "=r"(r[1]), "=r"(r[2]), "=r"(r[3]) : "r"(addr));
}
// not volatile: lets ptxas schedule HMMA around FMA/MUFU chains
__device__ __forceinline__ void mma_f16(float c[4], const uint32_t a[4],
                                        uint32_t b0, uint32_t b1) {
    asm("mma.sync.aligned.m16n8k16.row.col.f32.f16.f16.f32 "
        "{%0,%1,%2,%3}, {%4,%5,%6,%7}, {%8,%9}, {%0,%1,%2,%3};"
        : "+f"(c[0]), "+f"(c[1]), "+f"(c[2]), "+f"(c[3])
        : "r"(a[0]), "r"(a[1]), "r"(a[2]), "r"(a[3]), "r"(b0), "r"(b1));
}
__device__ __forceinline__ uint32_t packh(float lo, float hi) {
    uint32_t r;
    asm("cvt.rn.f16x2.f32 %0, %1, %2;" : "=r"(r) : "f"(hi), "f"(lo));
    return r;
}

// ================= pre-pass: K,V fp32 -> fp16 =================
__global__ __launch_bounds__(256)
void prep_kernel(const float* __restrict__ Kg, const float* __restrict__ Vg)
{
    const int i = blockIdx.x * 256 + threadIdx.x;      // per float4
    const int t = blockIdx.y;                          // 0=K 1=V
    const float4* src = (t == 0) ? (const float4*)Kg : (const float4*)Vg;
    uint2* hi = (t == 0) ? (uint2*)gKhi : (uint2*)gVhi;

    float4 v = src[i];
    uint2 h;
    h.x = packh(v.x, v.y);
    h.y = packh(v.z, v.w);
    hi[i] = h;
}

// ================= main attention kernel =================
__global__ __launch_bounds__(NTHR, 2)
void fattn_mma_kernel(float* __restrict__ Og, const float* __restrict__ Qg)
{
    extern __shared__ __align__(1024) uint8_t smem[];
    const uint32_t sb = smem_u32(smem);

    const int tid  = threadIdx.x;
    const int w    = tid >> 5;           // 0..3
    const int lane = tid & 31;
    const int lr   = lane & 15;
    const int lc   = (lane >> 4) << 3;
    const int quad = lane & 3;

    const int qt = (gridDim.x - 1) - blockIdx.x;   // heavy tiles first
    const int bh = blockIdx.y;
    const size_t rowbase = (size_t)bh * SEQ;       // 128B-row index base

    const int last = 2 * qt + 1;                   // kv tiles 0..2qt+1 (BM=2*BN)

    // hoisted swizzled address components:
    // swz(row*128 + col) == row*128 + (col ^ ((lr&7)<<4))  for col in [0,128)
    const uint32_t xorp = (uint32_t)((lr & 7) << 4);
    uint32_t rowoff[4], coloff[4];
    #pragma unroll
    for (int g = 0; g < 4; g++) {
        rowoff[g] = (uint32_t)((g * 16 + lr) * 128);
        coloff[g] = ((uint32_t)(g * 32 + lc * 2)) ^ xorp;
    }

    // tile issuer: one 16KB stage (KHI|VHI); 8 cp.async per thread
    auto issue_tile = [&](int kt) {
        const size_t tb = (rowbase + (size_t)kt * BN) * 128;
        const uint8_t* kh = gKhi + tb;
        const uint8_t* vh = gVhi + tb;
        const uint32_t stg = sb + (uint32_t)(kt & 3) * STAGE;
        #pragma unroll
        for (int j = 0; j < 4; j++) {
            uint32_t off = ((uint32_t)(tid + j * NTHR)) << 4;
            uint32_t so  = stg + swz(off);
            cpa16(so + P_KHI, kh + off);
            cpa16(so + P_VHI, vh + off);
        }
        CP_COMMIT();
    };

    issue_tile(0);                      // tile 0 -> stage 0
    issue_tile(1);                      // tile 1 -> stage 1 (last >= 1 always)

    // ---- Q: 128 rows, load fp32, scale, fp16 pack into stage-2 region (16KB) ----
    // Stage 2 is first overwritten by issue_tile(2) inside the loop (after BAR(0)).
    {
        const float* Qb = Qg + (rowbase + (size_t)qt * BM) * DH;
        #pragma unroll
        for (int it = 0; it < 16; it++) {
            int i  = tid + it * NTHR;   // 0..2047 float4
            int r  = i >> 4;
            int c4 = (i & 15) << 2;
            float4 v = *(const float4*)(Qb + r * DH + c4);
            uint2 h;
            h.x = packh(v.x * QSCALE, v.y * QSCALE);
            h.y = packh(v.z * QSCALE, v.w * QSCALE);
            *(uint2*)(smem + 2 * STAGE + swz((uint32_t)(r * 128 + c4 * 2))) = h;
        }
    }
    __syncthreads();

    // persistent Q fragments for both halves (rows h*64 + w*16 + lr)
    uint32_t qh[2][4][4];
    #pragma unroll
    for (int h = 0; h < 2; h++) {
        uint32_t qro = (uint32_t)((h * 64 + w * 16 + lr) * 128);
        #pragma unroll
        for (int ks = 0; ks < 4; ks++)
            ldsm4(qh[h][ks], sb + 2 * STAGE + qro + coloff[ks]);
    }

    float o[2][8][4];
    #pragma unroll
    for (int h = 0; h < 2; h++)
        #pragma unroll
        for (int n = 0; n < 8; n++)
            #pragma unroll
            for (int j = 0; j < 4; j++) o[h][n][j] = 0.f;
    float ol[2][4] = {{0.f,0.f,0.f,0.f},{0.f,0.f,0.f,0.f}};
    float m0[2] = {-1e30f, -1e30f}, m1[2] = {-1e30f, -1e30f};

    int qg0[2];
    #pragma unroll
    for (int h = 0; h < 2; h++)
        qg0[h] = qt * BM + h * 64 + w * 16 + (lane >> 2);

    for (int kt = 0; kt <= last; kt++) {
        if (kt < last) { CP_WAIT(1); } else { CP_WAIT(0); }
        __syncthreads();                 // single barrier: publish + WAR guard
        if (kt + 2 <= last) issue_tile(kt + 2);

        const uint32_t stg = sb + (uint32_t)(kt & 3) * STAGE;

        // ---- S[h] = Q[h].Khi — each K fragment feeds BOTH halves ----
        float s[2][8][4];
        #pragma unroll
        for (int h = 0; h < 2; h++)
            #pragma unroll
            for (int n = 0; n < 8; n++)
                #pragma unroll
                for (int j = 0; j < 4; j++) s[h][n][j] = 0.f;

        #pragma unroll
        for (int ks = 0; ks < 4; ks++) {
            #pragma unroll
            for (int kg = 0; kg < 4; kg++) {
                uint32_t bhf[4];
                ldsm4(bhf, stg + P_KHI + rowoff[kg] + coloff[ks]);
                #pragma unroll
                for (int h = 0; h < 2; h++) {
                    mma_f16(s[h][2*kg],   qh[h][ks], bhf[0], bhf[2]);
                    mma_f16(s[h][2*kg+1], qh[h][ks], bhf[1], bhf[3]);
                }
            }
        }

        // ---- causal mask (tiles 2qt, 2qt+1 only) ----
        if (kt >= 2 * qt) {
            #pragma unroll
            for (int h = 0; h < 2; h++)
                #pragma unroll
                for (int n = 0; n < 8; n++) {
                    int kb = kt * BN + n * 8 + quad * 2;
                    if (kb     > qg0[h])     s[h][n][0] = -30000.f;
                    if (kb + 1 > qg0[h])     s[h][n][1] = -30000.f;
                    if (kb     > qg0[h] + 8) s[h][n][2] = -30000.f;
                    if (kb + 1 > qg0[h] + 8) s[h][n][3] = -30000.f;
                }
        }

        // ---- online softmax (log2 domain), both halves, packed max reduce ----
        float mxa[2], mxb[2];
        #pragma unroll
        for (int h = 0; h < 2; h++) {
            float a = s[h][0][0], b = s[h][0][2];
            #pragma unroll
            for (int n = 0; n < 8; n++) {
                a = fmaxf(a, fmaxf(s[h][n][0], s[h][n][1]));
                b = fmaxf(b, fmaxf(s[h][n][2], s[h][n][3]));
            }
            uint32_t mxp = packh(a, b);
            mxp = maxh2(mxp, __shfl_xor_sync(0xffffffffu, mxp, 1));
            mxp = maxh2(mxp, __shfl_xor_sync(0xffffffffu, mxp, 2));
            mxa[h] = h2lo_f32(mxp);
            mxb[h] = h2hi_f32(mxp);
        }

        if (__any_sync(0xffffffffu, (mxa[0] > m0[0]) || (mxb[0] > m1[0]) ||
                                    (mxa[1] > m0[1]) || (mxb[1] > m1[1]))) {
            #pragma unroll
            for (int h = 0; h < 2; h++) {
                float mn0 = fmaxf(m0[h], mxa[h]), mn1 = fmaxf(m1[h], mxb[h]);
                float a0 = ex2(m0[h] - mn0), a1 = ex2(m1[h] - mn1);
                m0[h] = mn0; m1[h] = mn1;
                #pragma unroll
                for (int n = 0; n < 8; n++) {
                    o[h][n][0] *= a0; o[h][n][1] *= a0;
                    o[h][n][2] *= a1; o[h][n][3] *= a1;
                }
                ol[h][0] *= a0; ol[h][1] *= a0;
                ol[h][2] *= a1; ol[h][3] *= a1;
            }
        }

        // ---- P[h] = exp2(s - m) in fp16x2 A-fragments ----
        uint32_t pa[2][4][4];
        #pragma unroll
        for (int h = 0; h < 2; h++)
            #pragma unroll
            for (int j = 0; j < 4; j++) {
                pa[h][j][0] = ex2h2(packh(s[h][2*j][0]   - m0[h], s[h][2*j][1]   - m0[h]));
                pa[h][j][1] = ex2h2(packh(s[h][2*j][2]   - m1[h], s[h][2*j][3]   - m1[h]));
                pa[h][j][2] = ex2h2(packh(s[h][2*j+1][0] - m0[h], s[h][2*j+1][1] - m0[h]));
                pa[h][j][3] = ex2h2(packh(s[h][2*j+1][2] - m1[h], s[h][2*j+1][3] - m1[h]));
            }

        // ---- ol += P.1 ; O += P.Vhi — each V fragment feeds BOTH halves ----
        #pragma unroll
        for (int ks = 0; ks < 4; ks++) {
            mma_f16(ol[0], pa[0][ks], ONESH2, ONESH2);
            mma_f16(ol[1], pa[1][ks], ONESH2, ONESH2);
            #pragma unroll
            for (int dg = 0; dg < 4; dg++) {
                uint32_t vhf[4];
                ldsm4t(vhf, stg + P_VHI + rowoff[ks] + coloff[dg]);
                #pragma unroll
                for (int h = 0; h < 2; h++) {
                    mma_f16(o[h][2*dg],   pa[h][ks], vhf[0], vhf[1]);
                    mma_f16(o[h][2*dg+1], pa[h][ks], vhf[2], vhf[3]);
                }
            }
        }
    }

    // ---- epilogue: normalize by ones-column sums, both halves ----
    #pragma unroll
    for (int h = 0; h < 2; h++) {
        float inv0 = 1.0f / ol[h][0], inv1 = 1.0f / ol[h][2];
        float* Orow0 = Og + (rowbase + qg0[h]) * DH;
        float* Orow1 = Orow0 + 8 * DH;
        #pragma unroll
        for (int n = 0; n < 8; n++) {
            int d = n * 8 + quad * 2;
            *(float2*)(Orow0 + d) = make_float2(o[h][n][0] * inv0, o[h][n][1] * inv0);
            *(float2*)(Orow1 + d) = make_float2(o[h][n][2] * inv1, o[h][n][3] * inv1);
        }
    }
}

extern "C" void kernel_launch(void* const* d_in, const int* in_sizes, int n_in,
                              void* d_out, int out_size)
{
    const float* Q = (const float*)d_in[0];
    const float* K = (const float*)d_in[1];
    const float* V = (const float*)d_in[2];
    float* O = (float*)d_out;

    dim3 pgrid(NELEM / 4 / 256, 2);     // (4096, 2): K and V
    prep_kernel<<<pgrid, 256>>>(K, V);

    cudaFuncSetAttribute(fattn_mma_kernel,
                         cudaFuncAttributeMaxDynamicSharedMemorySize, SMEM_BYTES);
    dim3 grid(SEQ / BM, BHN);           // (16, 32)
    fattn_mma_kernel<<<grid, NTHR, SMEM_BYTES>>>(O, Q);
}